// round 4
// baseline (speedup 1.0000x reference)
#include <cuda_runtime.h>
#include <math.h>

// Problem dims
#define Bk 64
#define Tk 256
#define Dk 512
#define Hk 1024
#define Gk 3072   // 3*H
#define Ok 64
#define BT 16384  // B*T

typedef unsigned long long ull;

// -------- device scratch (no allocation allowed; __device__ globals are the workaround)
__device__ float g_gates[(long)BT * Gk];     // [T][B][3H], row r = t*B + b   (201 MB)
__device__ float g_hs[(long)Tk * Bk * Hk];   // [T][B][H] hidden states       (64 MB)
__device__ float g_h0[Bk * Hk];              // zero initial hidden state
__device__ float g_ghp[4 * Bk * Gk];         // K-split partials [ks][B][3H]  (3 MB)

// -------- packed f32x2 helpers (Blackwell FFMA2: 2x fp32 FMA throughput, exact fp32)
__device__ __forceinline__ ull ffma2(ull a, ull b, ull c) {
  ull d;
  asm("fma.rn.f32x2 %0, %1, %2, %3;" : "=l"(d) : "l"(a), "l"(b), "l"(c));
  return d;
}
__device__ __forceinline__ ull pack2(float lo, float hi) {
  ull d; asm("mov.b64 %0, {%1, %2};" : "=l"(d) : "f"(lo), "f"(hi)); return d;
}
__device__ __forceinline__ float2 unpack2(ull v) {
  float2 r; asm("mov.b64 {%0, %1}, %2;" : "=f"(r.x), "=f"(r.y) : "l"(v)); return r;
}
__device__ __forceinline__ float sigmoidf_(float x) { return 1.0f / (1.0f + expf(-x)); }

// ============================================================================
// Kernel 0: zero the initial hidden state (d_out-independent, deterministic)
// ============================================================================
__global__ void zero_h0_kernel() {
  int i = blockIdx.x * blockDim.x + threadIdx.x;
  if (i < Bk * Hk) g_h0[i] = 0.0f;
}

// ============================================================================
// Kernel 1: gates_x[r][c] = dot(emb[tok(r)], W_ih[c]) + b_ih[c]
//   r = t*B + b,  tok(r) = x[b*T + t]
//   GEMM M=16384 N=3072 K=512; block tile 128x64x32, 256 thr, 8x4 micro (f32x2)
// ============================================================================
__global__ __launch_bounds__(256) void gates_kernel(
    const int* __restrict__ x, const float* __restrict__ emb,
    const float* __restrict__ W_ih, const float* __restrict__ b_ih) {
  __shared__ __align__(16) float Xs[32][128];
  __shared__ __align__(16) float Ws[32][64];
  __shared__ int toks[128];

  const int tid = threadIdx.x;
  const int r0 = blockIdx.x * 128;
  const int c0 = blockIdx.y * 64;

  if (tid < 128) {
    int r = r0 + tid;
    toks[tid] = x[(r & 63) * Tk + (r >> 6)];  // b = r&63, t = r>>6
  }
  __syncthreads();

  ull acc[4][4] = {};  // m-pairs (8 rows) x 4 cols
  const int m0 = (tid & 15) * 8;
  const int n0 = (tid >> 4) * 4;

  for (int kc = 0; kc < Dk; kc += 32) {
    // load X tile (transposed [k][m]) via gathered emb rows
#pragma unroll
    for (int i = 0; i < 4; i++) {
      int q = tid + i * 256;
      int m = q & 127, kq = q >> 7;
      float4 v = *reinterpret_cast<const float4*>(
          &emb[(long)toks[m] * Dk + kc + kq * 4]);
      Xs[kq * 4 + 0][m] = v.x; Xs[kq * 4 + 1][m] = v.y;
      Xs[kq * 4 + 2][m] = v.z; Xs[kq * 4 + 3][m] = v.w;
    }
    // load W tile (transposed [k][n])
#pragma unroll
    for (int i = 0; i < 2; i++) {
      int q = tid + i * 256;
      int n = q & 63, kq = q >> 6;
      float4 v = *reinterpret_cast<const float4*>(
          &W_ih[(long)(c0 + n) * Dk + kc + kq * 4]);
      Ws[kq * 4 + 0][n] = v.x; Ws[kq * 4 + 1][n] = v.y;
      Ws[kq * 4 + 2][n] = v.z; Ws[kq * 4 + 3][n] = v.w;
    }
    __syncthreads();

#pragma unroll
    for (int k = 0; k < 32; k++) {
      const ull* ap = reinterpret_cast<const ull*>(&Xs[k][m0]);
      ull av[4];
      av[0] = ap[0]; av[1] = ap[1]; av[2] = ap[2]; av[3] = ap[3];
      float4 bv = *reinterpret_cast<const float4*>(&Ws[k][n0]);
      ull bb[4];
      bb[0] = pack2(bv.x, bv.x); bb[1] = pack2(bv.y, bv.y);
      bb[2] = pack2(bv.z, bv.z); bb[3] = pack2(bv.w, bv.w);
#pragma unroll
      for (int i = 0; i < 4; i++)
#pragma unroll
        for (int j = 0; j < 4; j++)
          acc[i][j] = ffma2(av[i], bb[j], acc[i][j]);
    }
    __syncthreads();
  }

  const float bs0 = b_ih[c0 + n0 + 0], bs1 = b_ih[c0 + n0 + 1];
  const float bs2 = b_ih[c0 + n0 + 2], bs3 = b_ih[c0 + n0 + 3];
#pragma unroll
  for (int i = 0; i < 4; i++) {
    float2 u0 = unpack2(acc[i][0]), u1 = unpack2(acc[i][1]);
    float2 u2 = unpack2(acc[i][2]), u3 = unpack2(acc[i][3]);
    long rowa = (long)(r0 + m0 + 2 * i) * Gk + c0 + n0;
    float4 lo = make_float4(u0.x + bs0, u1.x + bs1, u2.x + bs2, u3.x + bs3);
    float4 hi = make_float4(u0.y + bs0, u1.y + bs1, u2.y + bs2, u3.y + bs3);
    *reinterpret_cast<float4*>(&g_gates[rowa]) = lo;
    *reinterpret_cast<float4*>(&g_gates[rowa + Gk]) = hi;
  }
}

// ============================================================================
// Kernel 2 (per step): partial gh = h_{t-1} @ W_hhᵀ, K-split x4
//   grid (48, 4): 64-col tile x 256-K slice; block 64x64x256, 256 thr, 4x4 micro
// ============================================================================
__global__ __launch_bounds__(256) void step_gemm(const float* __restrict__ W_hh, int t) {
  __shared__ __align__(16) float Hs[32][64];
  __shared__ __align__(16) float Ws[32][64];

  const float* __restrict__ h = (t == 0) ? g_h0 : (g_hs + (long)(t - 1) * Bk * Hk);
  const int tid = threadIdx.x;
  const int c0 = blockIdx.x * 64;
  const int k0 = blockIdx.y * 256;

  ull acc[2][4] = {};  // m-pairs (4 batch rows) x 4 cols
  const int m0 = (tid & 15) * 4;
  const int n0 = (tid >> 4) * 4;

  for (int kc = 0; kc < 256; kc += 32) {
#pragma unroll
    for (int i = 0; i < 2; i++) {
      int q = tid + i * 256;
      int b = q & 63, kq = q >> 6;
      float4 v = *reinterpret_cast<const float4*>(&h[b * Hk + k0 + kc + kq * 4]);
      Hs[kq * 4 + 0][b] = v.x; Hs[kq * 4 + 1][b] = v.y;
      Hs[kq * 4 + 2][b] = v.z; Hs[kq * 4 + 3][b] = v.w;
      float4 w = *reinterpret_cast<const float4*>(
          &W_hh[(long)(c0 + b) * Hk + k0 + kc + kq * 4]);
      Ws[kq * 4 + 0][b] = w.x; Ws[kq * 4 + 1][b] = w.y;
      Ws[kq * 4 + 2][b] = w.z; Ws[kq * 4 + 3][b] = w.w;
    }
    __syncthreads();

#pragma unroll
    for (int k = 0; k < 32; k++) {
      const ull* ap = reinterpret_cast<const ull*>(&Hs[k][m0]);
      ull a0 = ap[0], a1 = ap[1];
      float4 bv = *reinterpret_cast<const float4*>(&Ws[k][n0]);
      ull bb[4];
      bb[0] = pack2(bv.x, bv.x); bb[1] = pack2(bv.y, bv.y);
      bb[2] = pack2(bv.z, bv.z); bb[3] = pack2(bv.w, bv.w);
#pragma unroll
      for (int j = 0; j < 4; j++) {
        acc[0][j] = ffma2(a0, bb[j], acc[0][j]);
        acc[1][j] = ffma2(a1, bb[j], acc[1][j]);
      }
    }
    __syncthreads();
  }

  float* gp = g_ghp + (long)blockIdx.y * (Bk * Gk);
#pragma unroll
  for (int i = 0; i < 2; i++) {
    float2 u0 = unpack2(acc[i][0]), u1 = unpack2(acc[i][1]);
    float2 u2 = unpack2(acc[i][2]), u3 = unpack2(acc[i][3]);
    int ba = m0 + 2 * i;
    float4 lo = make_float4(u0.x, u1.x, u2.x, u3.x);
    float4 hi = make_float4(u0.y, u1.y, u2.y, u3.y);
    *reinterpret_cast<float4*>(&gp[(long)ba * Gk + c0 + n0]) = lo;
    *reinterpret_cast<float4*>(&gp[(long)(ba + 1) * Gk + c0 + n0]) = hi;
  }
}

// ============================================================================
// Kernel 3 (per step): reduce partials + GRU gate nonlinearity -> h_t
// ============================================================================
__global__ __launch_bounds__(256) void step_elem(const float* __restrict__ b_hh, int t) {
  const int i = blockIdx.x * 256 + threadIdx.x;  // 65536 threads
  const int b = i >> 10;
  const int j = i & 1023;

  float hr = 0.0f, hz = 0.0f, hn = 0.0f;
#pragma unroll
  for (int s = 0; s < 4; s++) {
    const float* gp = g_ghp + (long)(s * Bk + b) * Gk + j;
    hr += gp[0];
    hz += gp[1024];
    hn += gp[2048];
  }

  const float* gx = g_gates + (long)(t * Bk + b) * Gk + j;
  float r = sigmoidf_(gx[0]    + hr + b_hh[j]);
  float z = sigmoidf_(gx[1024] + hz + b_hh[j + 1024]);
  float n = tanhf(gx[2048] + r * (hn + b_hh[j + 2048]));

  const float* hprev = (t == 0) ? g_h0 : (g_hs + (long)(t - 1) * Bk * Hk);
  float hnew = (1.0f - z) * n + z * hprev[i];
  g_hs[(long)t * Bk * Hk + i] = hnew;
}

// ============================================================================
// Kernel 4: logits = hs @ W_fcᵀ + b_fc; sigmoid; labels. One block per t.
//   out layout: proba [B][T][O] then labels [B][T][O]
//   CRITICAL: label = (computed fp32 proba > 0.5f), NOT (logit > 0) — the
//   reference rounds sigmoid to fp32 first; sigmoid(tiny positive x) rounds
//   to exactly 0.5f (expf(-x) rounds to 1.0f), giving label 0 for logit > 0.
// ============================================================================
__global__ __launch_bounds__(256) void fc_kernel(const float* __restrict__ W_fc,
                                                 const float* __restrict__ b_fc,
                                                 float* __restrict__ out,
                                                 int write_labels) {
  __shared__ __align__(16) float Hs[32][64];
  __shared__ __align__(16) float Ws[32][64];

  const int t = blockIdx.x;
  const int tid = threadIdx.x;
  const float* __restrict__ hb = g_hs + (long)t * Bk * Hk;

  ull acc[2][4] = {};
  const int m0 = (tid & 15) * 4;   // batch rows
  const int n0 = (tid >> 4) * 4;   // output cols

  for (int kc = 0; kc < Hk; kc += 32) {
#pragma unroll
    for (int i = 0; i < 2; i++) {
      int q = tid + i * 256;
      int b = q & 63, kq = q >> 6;
      float4 v = *reinterpret_cast<const float4*>(&hb[b * Hk + kc + kq * 4]);
      Hs[kq * 4 + 0][b] = v.x; Hs[kq * 4 + 1][b] = v.y;
      Hs[kq * 4 + 2][b] = v.z; Hs[kq * 4 + 3][b] = v.w;
      float4 w = *reinterpret_cast<const float4*>(&W_fc[(long)b * Hk + kc + kq * 4]);
      Ws[kq * 4 + 0][b] = w.x; Ws[kq * 4 + 1][b] = w.y;
      Ws[kq * 4 + 2][b] = w.z; Ws[kq * 4 + 3][b] = w.w;
    }
    __syncthreads();

#pragma unroll
    for (int k = 0; k < 32; k++) {
      const ull* ap = reinterpret_cast<const ull*>(&Hs[k][m0]);
      ull a0 = ap[0], a1 = ap[1];
      float4 bv = *reinterpret_cast<const float4*>(&Ws[k][n0]);
      ull bb[4];
      bb[0] = pack2(bv.x, bv.x); bb[1] = pack2(bv.y, bv.y);
      bb[2] = pack2(bv.z, bv.z); bb[3] = pack2(bv.w, bv.w);
#pragma unroll
      for (int j = 0; j < 4; j++) {
        acc[0][j] = ffma2(a0, bb[j], acc[0][j]);
        acc[1][j] = ffma2(a1, bb[j], acc[1][j]);
      }
    }
    __syncthreads();
  }

  const float bs0 = b_fc[n0 + 0], bs1 = b_fc[n0 + 1];
  const float bs2 = b_fc[n0 + 2], bs3 = b_fc[n0 + 3];
#pragma unroll
  for (int i = 0; i < 2; i++) {
    float2 u0 = unpack2(acc[i][0]), u1 = unpack2(acc[i][1]);
    float2 u2 = unpack2(acc[i][2]), u3 = unpack2(acc[i][3]);
    float lg[2][4] = {
        {u0.x + bs0, u1.x + bs1, u2.x + bs2, u3.x + bs3},
        {u0.y + bs0, u1.y + bs1, u2.y + bs2, u3.y + bs3}};
#pragma unroll
    for (int p = 0; p < 2; p++) {
      int b = m0 + 2 * i + p;
      long base = ((long)b * Tk + t) * Ok + n0;
      float4 pr = make_float4(sigmoidf_(lg[p][0]), sigmoidf_(lg[p][1]),
                              sigmoidf_(lg[p][2]), sigmoidf_(lg[p][3]));
      *reinterpret_cast<float4*>(&out[base]) = pr;
      if (write_labels) {
        // label derived from the ROUNDED fp32 proba (matches reference exactly)
        float4 lb = make_float4(pr.x > 0.5f ? 1.0f : 0.0f,
                                pr.y > 0.5f ? 1.0f : 0.0f,
                                pr.z > 0.5f ? 1.0f : 0.0f,
                                pr.w > 0.5f ? 1.0f : 0.0f);
        *reinterpret_cast<float4*>(&out[(long)BT * Ok + base]) = lb;
      }
    }
  }
}

// ============================================================================
// Launch: graph-capturable (kernel launches only, deterministic, no allocs)
// ============================================================================
extern "C" void kernel_launch(void* const* d_in, const int* in_sizes, int n_in,
                              void* d_out, int out_size) {
  const int*   x    = (const int*)d_in[0];
  const float* emb  = (const float*)d_in[1];
  const float* W_ih = (const float*)d_in[2];
  const float* W_hh = (const float*)d_in[3];
  const float* b_ih = (const float*)d_in[4];
  const float* b_hh = (const float*)d_in[5];
  const float* W_fc = (const float*)d_in[6];
  const float* b_fc = (const float*)d_in[7];
  float* out = (float*)d_out;

  zero_h0_kernel<<<64, 1024>>>();

  // gates_x = gather(emb, x) @ W_ih^T + b_ih   [16384 x 3072]
  gates_kernel<<<dim3(128, 48), 256>>>(x, emb, W_ih, b_ih);

  // sequential GRU recurrence
  for (int t = 0; t < Tk; t++) {
    step_gemm<<<dim3(48, 4), 256>>>(W_hh, t);
    step_elem<<<256, 256>>>(b_hh, t);
  }

  const int write_labels = (out_size >= 2 * BT * Ok) ? 1 : 0;
  fc_kernel<<<256, 256>>>(W_fc, b_fc, out, write_labels);
}

// round 5
// speedup vs baseline: 1.0019x; 1.0019x over previous
#include <cuda_runtime.h>
#include <math.h>

// Problem dims
#define Bk 64
#define Tk 256
#define Dk 512
#define Hk 1024
#define Gk 3072   // 3*H
#define Ok 64
#define BT 16384  // B*T

typedef unsigned long long ull;

// -------- device scratch (no allocation allowed; __device__ globals are the workaround)
__device__ float g_gates[(long)BT * Gk];     // [T][B][3H], row r = t*B + b   (201 MB)
__device__ float g_hs[(long)Tk * Bk * Hk];   // [T][B][H] hidden states       (64 MB)
__device__ float g_h0[Bk * Hk];              // zero initial hidden state
__device__ float g_ghp[4 * Bk * Gk];         // K-split partials [ks][B][3H]  (3 MB)

// -------- packed f32x2 helpers (Blackwell FFMA2: 2x fp32 FMA throughput, exact fp32)
__device__ __forceinline__ ull ffma2(ull a, ull b, ull c) {
  ull d;
  asm("fma.rn.f32x2 %0, %1, %2, %3;" : "=l"(d) : "l"(a), "l"(b), "l"(c));
  return d;
}
__device__ __forceinline__ ull pack2(float lo, float hi) {
  ull d; asm("mov.b64 %0, {%1, %2};" : "=l"(d) : "f"(lo), "f"(hi)); return d;
}
__device__ __forceinline__ float2 unpack2(ull v) {
  float2 r; asm("mov.b64 {%0, %1}, %2;" : "=f"(r.x), "=f"(r.y) : "l"(v)); return r;
}
__device__ __forceinline__ float sigmoidf_(float x) { return 1.0f / (1.0f + expf(-x)); }

// ============================================================================
// Kernel 0: zero the initial hidden state (d_out-independent, deterministic)
// ============================================================================
__global__ void zero_h0_kernel() {
  int i = blockIdx.x * blockDim.x + threadIdx.x;
  if (i < Bk * Hk) g_h0[i] = 0.0f;
}

// ============================================================================
// Kernel 1: gates_x[r][c] = dot(emb[tok(r)], W_ih[c]) + b_ih[c]
//   r = t*B + b,  tok(r) = x[b*T + t]
//   GEMM M=16384 N=3072 K=512; block tile 128x64x32, 256 thr, 8x4 micro (f32x2)
// ============================================================================
__global__ __launch_bounds__(256) void gates_kernel(
    const int* __restrict__ x, const float* __restrict__ emb,
    const float* __restrict__ W_ih, const float* __restrict__ b_ih) {
  __shared__ __align__(16) float Xs[32][128];
  __shared__ __align__(16) float Ws[32][64];
  __shared__ int toks[128];

  const int tid = threadIdx.x;
  const int r0 = blockIdx.x * 128;
  const int c0 = blockIdx.y * 64;

  if (tid < 128) {
    int r = r0 + tid;
    toks[tid] = x[(r & 63) * Tk + (r >> 6)];  // b = r&63, t = r>>6
  }
  __syncthreads();

  ull acc[4][4] = {};  // m-pairs (8 rows) x 4 cols
  const int m0 = (tid & 15) * 8;
  const int n0 = (tid >> 4) * 4;

  for (int kc = 0; kc < Dk; kc += 32) {
    // load X tile (transposed [k][m]) via gathered emb rows
#pragma unroll
    for (int i = 0; i < 4; i++) {
      int q = tid + i * 256;
      int m = q & 127, kq = q >> 7;
      float4 v = *reinterpret_cast<const float4*>(
          &emb[(long)toks[m] * Dk + kc + kq * 4]);
      Xs[kq * 4 + 0][m] = v.x; Xs[kq * 4 + 1][m] = v.y;
      Xs[kq * 4 + 2][m] = v.z; Xs[kq * 4 + 3][m] = v.w;
    }
    // load W tile (transposed [k][n])
#pragma unroll
    for (int i = 0; i < 2; i++) {
      int q = tid + i * 256;
      int n = q & 63, kq = q >> 6;
      float4 v = *reinterpret_cast<const float4*>(
          &W_ih[(long)(c0 + n) * Dk + kc + kq * 4]);
      Ws[kq * 4 + 0][n] = v.x; Ws[kq * 4 + 1][n] = v.y;
      Ws[kq * 4 + 2][n] = v.z; Ws[kq * 4 + 3][n] = v.w;
    }
    __syncthreads();

#pragma unroll
    for (int k = 0; k < 32; k++) {
      const ull* ap = reinterpret_cast<const ull*>(&Xs[k][m0]);
      ull av[4];
      av[0] = ap[0]; av[1] = ap[1]; av[2] = ap[2]; av[3] = ap[3];
      float4 bv = *reinterpret_cast<const float4*>(&Ws[k][n0]);
      ull bb[4];
      bb[0] = pack2(bv.x, bv.x); bb[1] = pack2(bv.y, bv.y);
      bb[2] = pack2(bv.z, bv.z); bb[3] = pack2(bv.w, bv.w);
#pragma unroll
      for (int i = 0; i < 4; i++)
#pragma unroll
        for (int j = 0; j < 4; j++)
          acc[i][j] = ffma2(av[i], bb[j], acc[i][j]);
    }
    __syncthreads();
  }

  const float bs0 = b_ih[c0 + n0 + 0], bs1 = b_ih[c0 + n0 + 1];
  const float bs2 = b_ih[c0 + n0 + 2], bs3 = b_ih[c0 + n0 + 3];
#pragma unroll
  for (int i = 0; i < 4; i++) {
    float2 u0 = unpack2(acc[i][0]), u1 = unpack2(acc[i][1]);
    float2 u2 = unpack2(acc[i][2]), u3 = unpack2(acc[i][3]);
    long rowa = (long)(r0 + m0 + 2 * i) * Gk + c0 + n0;
    float4 lo = make_float4(u0.x + bs0, u1.x + bs1, u2.x + bs2, u3.x + bs3);
    float4 hi = make_float4(u0.y + bs0, u1.y + bs1, u2.y + bs2, u3.y + bs3);
    *reinterpret_cast<float4*>(&g_gates[rowa]) = lo;
    *reinterpret_cast<float4*>(&g_gates[rowa + Gk]) = hi;
  }
}

// ============================================================================
// Kernel 2 (per step): partial gh = h_{t-1} @ W_hhᵀ, K-split x4
//   grid (48, 4): 64-col tile x 256-K slice; block 64x64x256, 256 thr, 4x4 micro
// ============================================================================
__global__ __launch_bounds__(256) void step_gemm(const float* __restrict__ W_hh, int t) {
  __shared__ __align__(16) float Hs[32][64];
  __shared__ __align__(16) float Ws[32][64];

  const float* __restrict__ h = (t == 0) ? g_h0 : (g_hs + (long)(t - 1) * Bk * Hk);
  const int tid = threadIdx.x;
  const int c0 = blockIdx.x * 64;
  const int k0 = blockIdx.y * 256;

  ull acc[2][4] = {};  // m-pairs (4 batch rows) x 4 cols
  const int m0 = (tid & 15) * 4;
  const int n0 = (tid >> 4) * 4;

  for (int kc = 0; kc < 256; kc += 32) {
#pragma unroll
    for (int i = 0; i < 2; i++) {
      int q = tid + i * 256;
      int b = q & 63, kq = q >> 6;
      float4 v = *reinterpret_cast<const float4*>(&h[b * Hk + k0 + kc + kq * 4]);
      Hs[kq * 4 + 0][b] = v.x; Hs[kq * 4 + 1][b] = v.y;
      Hs[kq * 4 + 2][b] = v.z; Hs[kq * 4 + 3][b] = v.w;
      float4 w = *reinterpret_cast<const float4*>(
          &W_hh[(long)(c0 + b) * Hk + k0 + kc + kq * 4]);
      Ws[kq * 4 + 0][b] = w.x; Ws[kq * 4 + 1][b] = w.y;
      Ws[kq * 4 + 2][b] = w.z; Ws[kq * 4 + 3][b] = w.w;
    }
    __syncthreads();

#pragma unroll
    for (int k = 0; k < 32; k++) {
      const ull* ap = reinterpret_cast<const ull*>(&Hs[k][m0]);
      ull a0 = ap[0], a1 = ap[1];
      float4 bv = *reinterpret_cast<const float4*>(&Ws[k][n0]);
      ull bb[4];
      bb[0] = pack2(bv.x, bv.x); bb[1] = pack2(bv.y, bv.y);
      bb[2] = pack2(bv.z, bv.z); bb[3] = pack2(bv.w, bv.w);
#pragma unroll
      for (int j = 0; j < 4; j++) {
        acc[0][j] = ffma2(a0, bb[j], acc[0][j]);
        acc[1][j] = ffma2(a1, bb[j], acc[1][j]);
      }
    }
    __syncthreads();
  }

  float* gp = g_ghp + (long)blockIdx.y * (Bk * Gk);
#pragma unroll
  for (int i = 0; i < 2; i++) {
    float2 u0 = unpack2(acc[i][0]), u1 = unpack2(acc[i][1]);
    float2 u2 = unpack2(acc[i][2]), u3 = unpack2(acc[i][3]);
    int ba = m0 + 2 * i;
    float4 lo = make_float4(u0.x, u1.x, u2.x, u3.x);
    float4 hi = make_float4(u0.y, u1.y, u2.y, u3.y);
    *reinterpret_cast<float4*>(&gp[(long)ba * Gk + c0 + n0]) = lo;
    *reinterpret_cast<float4*>(&gp[(long)(ba + 1) * Gk + c0 + n0]) = hi;
  }
}

// ============================================================================
// Kernel 3 (per step): reduce partials + GRU gate nonlinearity -> h_t
// ============================================================================
__global__ __launch_bounds__(256) void step_elem(const float* __restrict__ b_hh, int t) {
  const int i = blockIdx.x * 256 + threadIdx.x;  // 65536 threads
  const int b = i >> 10;
  const int j = i & 1023;

  float hr = 0.0f, hz = 0.0f, hn = 0.0f;
#pragma unroll
  for (int s = 0; s < 4; s++) {
    const float* gp = g_ghp + (long)(s * Bk + b) * Gk + j;
    hr += gp[0];
    hz += gp[1024];
    hn += gp[2048];
  }

  const float* gx = g_gates + (long)(t * Bk + b) * Gk + j;
  float r = sigmoidf_(gx[0]    + hr + b_hh[j]);
  float z = sigmoidf_(gx[1024] + hz + b_hh[j + 1024]);
  float n = tanhf(gx[2048] + r * (hn + b_hh[j + 2048]));

  const float* hprev = (t == 0) ? g_h0 : (g_hs + (long)(t - 1) * Bk * Hk);
  float hnew = (1.0f - z) * n + z * hprev[i];
  g_hs[(long)t * Bk * Hk + i] = hnew;
}

// ============================================================================
// Kernel 4: logits = hs @ W_fcᵀ + b_fc; sigmoid; labels. One block per t.
//   out layout: proba [B][T][O] then labels [B][T][O]
//   CRITICAL: label = (computed fp32 proba > 0.5f), NOT (logit > 0) — the
//   reference rounds sigmoid to fp32 first; sigmoid(tiny positive x) rounds
//   to exactly 0.5f (expf(-x) rounds to 1.0f), giving label 0 for logit > 0.
// ============================================================================
__global__ __launch_bounds__(256) void fc_kernel(const float* __restrict__ W_fc,
                                                 const float* __restrict__ b_fc,
                                                 float* __restrict__ out,
                                                 int write_labels) {
  __shared__ __align__(16) float Hs[32][64];
  __shared__ __align__(16) float Ws[32][64];

  const int t = blockIdx.x;
  const int tid = threadIdx.x;
  const float* __restrict__ hb = g_hs + (long)t * Bk * Hk;

  ull acc[2][4] = {};
  const int m0 = (tid & 15) * 4;   // batch rows
  const int n0 = (tid >> 4) * 4;   // output cols

  for (int kc = 0; kc < Hk; kc += 32) {
#pragma unroll
    for (int i = 0; i < 2; i++) {
      int q = tid + i * 256;
      int b = q & 63, kq = q >> 6;
      float4 v = *reinterpret_cast<const float4*>(&hb[b * Hk + kc + kq * 4]);
      Hs[kq * 4 + 0][b] = v.x; Hs[kq * 4 + 1][b] = v.y;
      Hs[kq * 4 + 2][b] = v.z; Hs[kq * 4 + 3][b] = v.w;
      float4 w = *reinterpret_cast<const float4*>(&W_fc[(long)b * Hk + kc + kq * 4]);
      Ws[kq * 4 + 0][b] = w.x; Ws[kq * 4 + 1][b] = w.y;
      Ws[kq * 4 + 2][b] = w.z; Ws[kq * 4 + 3][b] = w.w;
    }
    __syncthreads();

#pragma unroll
    for (int k = 0; k < 32; k++) {
      const ull* ap = reinterpret_cast<const ull*>(&Hs[k][m0]);
      ull a0 = ap[0], a1 = ap[1];
      float4 bv = *reinterpret_cast<const float4*>(&Ws[k][n0]);
      ull bb[4];
      bb[0] = pack2(bv.x, bv.x); bb[1] = pack2(bv.y, bv.y);
      bb[2] = pack2(bv.z, bv.z); bb[3] = pack2(bv.w, bv.w);
#pragma unroll
      for (int j = 0; j < 4; j++) {
        acc[0][j] = ffma2(a0, bb[j], acc[0][j]);
        acc[1][j] = ffma2(a1, bb[j], acc[1][j]);
      }
    }
    __syncthreads();
  }

  const float bs0 = b_fc[n0 + 0], bs1 = b_fc[n0 + 1];
  const float bs2 = b_fc[n0 + 2], bs3 = b_fc[n0 + 3];
#pragma unroll
  for (int i = 0; i < 2; i++) {
    float2 u0 = unpack2(acc[i][0]), u1 = unpack2(acc[i][1]);
    float2 u2 = unpack2(acc[i][2]), u3 = unpack2(acc[i][3]);
    float lg[2][4] = {
        {u0.x + bs0, u1.x + bs1, u2.x + bs2, u3.x + bs3},
        {u0.y + bs0, u1.y + bs1, u2.y + bs2, u3.y + bs3}};
#pragma unroll
    for (int p = 0; p < 2; p++) {
      int b = m0 + 2 * i + p;
      long base = ((long)b * Tk + t) * Ok + n0;
      float4 pr = make_float4(sigmoidf_(lg[p][0]), sigmoidf_(lg[p][1]),
                              sigmoidf_(lg[p][2]), sigmoidf_(lg[p][3]));
      *reinterpret_cast<float4*>(&out[base]) = pr;
      if (write_labels) {
        // label derived from the ROUNDED fp32 proba (matches reference exactly)
        float4 lb = make_float4(pr.x > 0.5f ? 1.0f : 0.0f,
                                pr.y > 0.5f ? 1.0f : 0.0f,
                                pr.z > 0.5f ? 1.0f : 0.0f,
                                pr.w > 0.5f ? 1.0f : 0.0f);
        *reinterpret_cast<float4*>(&out[(long)BT * Ok + base]) = lb;
      }
    }
  }
}

// ============================================================================
// Launch: graph-capturable (kernel launches only, deterministic, no allocs)
// ============================================================================
extern "C" void kernel_launch(void* const* d_in, const int* in_sizes, int n_in,
                              void* d_out, int out_size) {
  const int*   x    = (const int*)d_in[0];
  const float* emb  = (const float*)d_in[1];
  const float* W_ih = (const float*)d_in[2];
  const float* W_hh = (const float*)d_in[3];
  const float* b_ih = (const float*)d_in[4];
  const float* b_hh = (const float*)d_in[5];
  const float* W_fc = (const float*)d_in[6];
  const float* b_fc = (const float*)d_in[7];
  float* out = (float*)d_out;

  zero_h0_kernel<<<64, 1024>>>();

  // gates_x = gather(emb, x) @ W_ih^T + b_ih   [16384 x 3072]
  gates_kernel<<<dim3(128, 48), 256>>>(x, emb, W_ih, b_ih);

  // sequential GRU recurrence
  for (int t = 0; t < Tk; t++) {
    step_gemm<<<dim3(48, 4), 256>>>(W_hh, t);
    step_elem<<<256, 256>>>(b_hh, t);
  }

  const int write_labels = (out_size >= 2 * BT * Ok) ? 1 : 0;
  fc_kernel<<<256, 256>>>(W_fc, b_fc, out, write_labels);
}